// round 2
// baseline (speedup 1.0000x reference)
#include <cuda_runtime.h>
#include <cuda_bf16.h>

#define B_  128
#define T_  64
#define N_  81
#define M_  128
#define G4_ 512

// scratch (static device globals — no allocs)
__device__ float g_z[B_ * G4_];            // h0@U_lstm + b_lstm     (128,512)
__device__ float g_hc[B_ * T_ * 2 * M_];   // [h;c]                  (128,64,256)
__device__ float g_A[B_ * T_ * T_];        // hc@We_w + We_b         (128,64,64)
__device__ float g_U[B_ * N_ * T_];        // einsum(X,Ue_w)+Ue_b    (128,81,64)
__device__ float g_alpha[B_ * T_ * N_];    // softmax scores         (128,64,81)

__device__ __forceinline__ float frcp(float x) {
    float r; asm("rcp.approx.ftz.f32 %0, %1;" : "=f"(r) : "f"(x)); return r;
}
__device__ __forceinline__ float sigm(float x) {
    return frcp(1.0f + __expf(-x));
}
__device__ __forceinline__ float tanha(float x) {
    return 2.0f * frcp(1.0f + __expf(-2.0f * x)) - 1.0f;
}

// ---------------------------------------------------------------------------
// K0: z[b,g] = b_lstm[g] + sum_k h0[b,k] * U_lstm[k,g]
// ---------------------------------------------------------------------------
__global__ void k_z(const float* __restrict__ h0,
                    const float* __restrict__ Ul,
                    const float* __restrict__ bl) {
    __shared__ float hs[M_];
    int b = blockIdx.x, g = threadIdx.x;           // 512 threads
    if (g < M_) hs[g] = h0[b * M_ + g];
    __syncthreads();
    float acc = bl[g];
#pragma unroll 8
    for (int k = 0; k < M_; k++) acc += hs[k] * Ul[k * G4_ + g];
    g_z[b * G4_ + g] = acc;
}

// ---------------------------------------------------------------------------
// K1: gates = X@W_lstm + z ; i,f,g,o -> c,h ; store hc = [h;c]
// grid = B*4 (quarter of T each), 128 threads (4 warps = 4 row-groups of 4 t)
// ---------------------------------------------------------------------------
__global__ void k_gates(const float* __restrict__ X,
                        const float* __restrict__ Wl,
                        const float* __restrict__ s0) {
    __shared__ float Xs[16 * N_];        // 16 t-rows of X
    __shared__ float Ws[N_ * 128];       // k x (gate*32 + c), one 32-col band
    int blk = blockIdx.x;
    int b = blk >> 2, tq = blk & 3;
    int t0 = tq * 16;
    int tid = threadIdx.x;               // 128
    for (int idx = tid; idx < 16 * N_; idx += 128) {
        int r = idx / N_, i = idx - r * N_;
        Xs[idx] = X[(b * T_ + t0 + r) * N_ + i];
    }
    int lane = tid & 31, rg = tid >> 5;  // rg = warp = row-group

    for (int mi = 0; mi < 4; mi++) {
        __syncthreads();
        for (int idx = tid; idx < N_ * 128; idx += 128) {
            int k = idx >> 7, j = idx & 127;
            int g = j >> 5, c = j & 31;
            Ws[idx] = Wl[k * G4_ + g * M_ + mi * 32 + c];
        }
        __syncthreads();

        float ai[4] = {0, 0, 0, 0}, af[4] = {0, 0, 0, 0};
        float ag[4] = {0, 0, 0, 0}, ao[4] = {0, 0, 0, 0};
#pragma unroll 3
        for (int k = 0; k < N_; k++) {
            float x0 = Xs[(rg * 4 + 0) * N_ + k];
            float x1 = Xs[(rg * 4 + 1) * N_ + k];
            float x2 = Xs[(rg * 4 + 2) * N_ + k];
            float x3 = Xs[(rg * 4 + 3) * N_ + k];
            float wi = Ws[k * 128 + 0  + lane];
            float wf = Ws[k * 128 + 32 + lane];
            float wg = Ws[k * 128 + 64 + lane];
            float wo = Ws[k * 128 + 96 + lane];
            ai[0] += x0 * wi; ai[1] += x1 * wi; ai[2] += x2 * wi; ai[3] += x3 * wi;
            af[0] += x0 * wf; af[1] += x1 * wf; af[2] += x2 * wf; af[3] += x3 * wf;
            ag[0] += x0 * wg; ag[1] += x1 * wg; ag[2] += x2 * wg; ag[3] += x3 * wg;
            ao[0] += x0 * wo; ao[1] += x1 * wo; ao[2] += x2 * wo; ao[3] += x3 * wo;
        }
        int mc = mi * 32 + lane;
        float zi = g_z[b * G4_ + 0 * M_ + mc];
        float zf = g_z[b * G4_ + 1 * M_ + mc];
        float zg = g_z[b * G4_ + 2 * M_ + mc];
        float zo = g_z[b * G4_ + 3 * M_ + mc];
        float sv = s0[b * M_ + mc];
#pragma unroll
        for (int r = 0; r < 4; r++) {
            int t = t0 + rg * 4 + r;
            float iv = sigm(ai[r] + zi);
            float fv = sigm(af[r] + zf);
            float gv = tanha(ag[r] + zg);
            float ov = sigm(ao[r] + zo);
            float cc = fv * sv + iv * gv;
            float hh = ov * tanha(cc);
            g_hc[(b * T_ + t) * 256 + mc]       = hh;
            g_hc[(b * T_ + t) * 256 + M_ + mc]  = cc;
        }
    }
}

// ---------------------------------------------------------------------------
// K2: A = hc @ We_w + We_b   (per b: 64x64, K=256)
// ---------------------------------------------------------------------------
__global__ void k_A(const float* __restrict__ Wew,
                    const float* __restrict__ Web) {
    __shared__ float hcs[64 * 65];
    __shared__ float Wes[64 * 64];
    int b = blockIdx.x;
    int tid = threadIdx.x;               // 256
    int rr = tid >> 4, cc = tid & 15;
    float acc[4][4];
    float wb[4];
#pragma unroll
    for (int j = 0; j < 4; j++) wb[j] = Web[cc * 4 + j];
#pragma unroll
    for (int i = 0; i < 4; i++)
#pragma unroll
        for (int j = 0; j < 4; j++) acc[i][j] = wb[j];

    for (int kc = 0; kc < 4; kc++) {
        __syncthreads();
        for (int idx = tid; idx < 64 * 64; idx += 256) {
            int t = idx >> 6, kk = idx & 63;
            hcs[t * 65 + kk] = g_hc[(b * T_ + t) * 256 + kc * 64 + kk];
        }
        for (int idx = tid; idx < 64 * 64; idx += 256)
            Wes[idx] = Wew[kc * 4096 + idx];
        __syncthreads();
#pragma unroll 4
        for (int k = 0; k < 64; k++) {
            float a[4], w[4];
#pragma unroll
            for (int i = 0; i < 4; i++) a[i] = hcs[(rr * 4 + i) * 65 + k];
#pragma unroll
            for (int j = 0; j < 4; j++) w[j] = Wes[k * 64 + cc * 4 + j];
#pragma unroll
            for (int i = 0; i < 4; i++)
#pragma unroll
                for (int j = 0; j < 4; j++) acc[i][j] += a[i] * w[j];
        }
    }
#pragma unroll
    for (int i = 0; i < 4; i++) {
        float4 v = make_float4(acc[i][0], acc[i][1], acc[i][2], acc[i][3]);
        *(float4*)&g_A[(b * T_ + rr * 4 + i) * 64 + cc * 4] = v;
    }
}

// ---------------------------------------------------------------------------
// KU: U[b,i,k] = sum_t X[b,t,i] * Ue_w[t,k] + Ue_b[k]
// ---------------------------------------------------------------------------
__global__ void k_U(const float* __restrict__ X,
                    const float* __restrict__ Uew,
                    const float* __restrict__ Ueb) {
    __shared__ float Xs[T_ * N_];
    __shared__ float Ues[T_ * 64];
    int b = blockIdx.x;
    int tid = threadIdx.x;               // 256
    for (int idx = tid; idx < T_ * N_; idx += 256) Xs[idx] = X[b * T_ * N_ + idx];
    for (int idx = tid; idx < T_ * 64; idx += 256) Ues[idx] = Uew[idx];
    __syncthreads();
    for (int g = tid; g < N_ * 16; g += 256) {
        int i = g >> 4, kq = g & 15;
        float4 acc = *(const float4*)&Ueb[kq * 4];
#pragma unroll 4
        for (int t = 0; t < T_; t++) {
            float x = Xs[t * N_ + i];
            float4 u = *(const float4*)&Ues[t * 64 + kq * 4];
            acc.x += x * u.x; acc.y += x * u.y; acc.z += x * u.z; acc.w += x * u.w;
        }
        *(float4*)&g_U[b * N_ * 64 + i * 64 + kq * 4] = acc;
    }
}

// ---------------------------------------------------------------------------
// K3: scores[b,t,i] = sum_k v[k]*tanh(A[b,t,k]+U[b,i,k]); softmax over i
// grid = B*2 (t-halves of 32), 256 threads
// ---------------------------------------------------------------------------
__global__ void k_score(const float* __restrict__ vew) {
    __shared__ float As[32 * 64];
    __shared__ float Us[N_ * 65];
    __shared__ float vs[64];
    __shared__ float sc[32 * N_];
    __shared__ float rm[32], rs[32];
    int blk = blockIdx.x;
    int b = blk >> 1, th = blk & 1;
    int tid = threadIdx.x;               // 256
    for (int idx = tid; idx < 2048; idx += 256)
        As[idx] = g_A[b * 4096 + th * 2048 + idx];
    for (int idx = tid; idx < N_ * 64; idx += 256) {
        int i = idx >> 6, k = idx & 63;
        Us[i * 65 + k] = g_U[b * N_ * 64 + idx];
    }
    if (tid < 64) vs[tid] = vew[tid];
    __syncthreads();

    for (int s = tid; s < 32 * N_; s += 256) {
        int t = s / N_, i = s - t * N_;
        const float* Ap = &As[t * 64];
        const float* Up = &Us[i * 65];
        float acc = 0.0f;
#pragma unroll 8
        for (int k = 0; k < 64; k++) acc += vs[k] * tanha(Ap[k] + Up[k]);
        sc[s] = acc;
    }
    __syncthreads();

    if (tid < 32) {
        int t = tid;
        float mx = -1e30f;
        for (int i = 0; i < N_; i++) mx = fmaxf(mx, sc[t * N_ + i]);
        float sum = 0.0f;
        for (int i = 0; i < N_; i++) sum += __expf(sc[t * N_ + i] - mx);
        rm[t] = mx; rs[t] = frcp(sum);
    }
    __syncthreads();

    for (int s = tid; s < 32 * N_; s += 256) {
        int t = s / N_;
        g_alpha[b * T_ * N_ + th * 32 * N_ + s] = __expf(sc[s] - rm[t]) * rs[t];
    }
}

// ---------------------------------------------------------------------------
// K4: out[t,b,tp,i] = X[b,tp,i] * alpha[b,t,i]  — scaled copy, float4 I/O
// grid = 8192 (b-major), 256 threads
// ---------------------------------------------------------------------------
__global__ void k_out(const float* __restrict__ X, float* __restrict__ out) {
    __shared__ float al[N_];
    int blk = blockIdx.x;
    int b = blk >> 6, t = blk & 63;
    int tid = threadIdx.x;               // 256
    if (tid < N_) al[tid] = g_alpha[b * T_ * N_ + t * N_ + tid];
    __syncthreads();
    const float4* X4 = (const float4*)(X + b * (T_ * N_));
    float4* O4 = (float4*)out + (size_t)(t * B_ + b) * 1296;
    for (int j4 = tid; j4 < 1296; j4 += 256) {
        float4 x = __ldg(&X4[j4]);
        int jb = j4 * 4;
        int i0 = jb % N_;
        int i1 = i0 + 1; if (i1 >= N_) i1 -= N_;
        int i2 = i1 + 1; if (i2 >= N_) i2 -= N_;
        int i3 = i2 + 1; if (i3 >= N_) i3 -= N_;
        float4 o;
        o.x = x.x * al[i0]; o.y = x.y * al[i1];
        o.z = x.z * al[i2]; o.w = x.w * al[i3];
        O4[j4] = o;
    }
}

// ---------------------------------------------------------------------------
extern "C" void kernel_launch(void* const* d_in, const int* in_sizes, int n_in,
                              void* d_out, int out_size) {
    const float* X   = (const float*)d_in[0];
    const float* h0  = (const float*)d_in[1];
    const float* s0  = (const float*)d_in[2];
    const float* Wl  = (const float*)d_in[3];
    const float* Ul  = (const float*)d_in[4];
    const float* bl  = (const float*)d_in[5];
    const float* Wew = (const float*)d_in[6];
    const float* Web = (const float*)d_in[7];
    const float* Uew = (const float*)d_in[8];
    const float* Ueb = (const float*)d_in[9];
    const float* vew = (const float*)d_in[10];
    // d_in[11] = ve_b: constant shift before softmax -> softmax-invariant, unused.
    float* out = (float*)d_out;

    k_z    <<<B_,      G4_>>>(h0, Ul, bl);
    k_gates<<<B_ * 4,  128>>>(X, Wl, s0);
    k_A    <<<B_,      256>>>(Wew, Web);
    k_U    <<<B_,      256>>>(X, Uew, Ueb);
    k_score<<<B_ * 2,  256>>>(vew);
    k_out  <<<B_ * T_, 256>>>(X, out);
    (void)in_sizes; (void)n_in; (void)out_size;
}

// round 3
// speedup vs baseline: 1.5115x; 1.5115x over previous
#include <cuda_runtime.h>

#define B_  128
#define T_  64
#define N_  81
#define M_  128
#define G4_ 512

// scratch (static device globals — no allocs)
__device__ float g_z[B_ * G4_];            // h0@U_lstm + b_lstm     (128,512)
__device__ float g_hc[B_ * T_ * 2 * M_];   // [h;c]                  (128,64,256)
__device__ float g_alpha[B_ * T_ * N_];    // softmax(scores)        (128,64,81)

__device__ __forceinline__ float frcp(float x) {
    float r; asm("rcp.approx.ftz.f32 %0, %1;" : "=f"(r) : "f"(x)); return r;
}
__device__ __forceinline__ float sigm(float x) {
    return frcp(1.0f + __expf(-x));
}
__device__ __forceinline__ float tanhe(float x) {           // exp-based, accurate
    return 2.0f * frcp(1.0f + __expf(-2.0f * x)) - 1.0f;
}
__device__ __forceinline__ float tanhap(float x) {          // HW tanh, 1 MUFU
    float r; asm("tanh.approx.f32 %0, %1;" : "=f"(r) : "f"(x)); return r;
}
__device__ __forceinline__ unsigned long long pk2(float a, float b) {
    unsigned long long r;
    asm("mov.b64 %0, {%1, %2};" : "=l"(r) : "f"(a), "f"(b)); return r;
}
__device__ __forceinline__ unsigned long long fma2(unsigned long long a,
                                                   unsigned long long b,
                                                   unsigned long long c) {
    unsigned long long d;
    asm("fma.rn.f32x2 %0, %1, %2, %3;" : "=l"(d) : "l"(a), "l"(b), "l"(c));
    return d;
}
__device__ __forceinline__ void unpk2(unsigned long long v, float& lo, float& hi) {
    asm("mov.b64 {%0, %1}, %2;" : "=f"(lo), "=f"(hi) : "l"(v));
}

// ---------------------------------------------------------------------------
// K0: z[b,g] = b_lstm[g] + sum_k h0[b,k] * U_lstm[k,g]
// ---------------------------------------------------------------------------
__global__ void k_z(const float* __restrict__ h0,
                    const float* __restrict__ Ul,
                    const float* __restrict__ bl) {
    __shared__ float hs[M_];
    int b = blockIdx.x, g = threadIdx.x;           // 512 threads
    if (g < M_) hs[g] = h0[b * M_ + g];
    __syncthreads();
    float acc = bl[g];
#pragma unroll 8
    for (int k = 0; k < M_; k++) acc += hs[k] * Ul[k * G4_ + g];
    g_z[b * G4_ + g] = acc;
}

// ---------------------------------------------------------------------------
// K1: gates = X@W_lstm + z ; LSTM cell ; store hc = [h;c]
// grid = B (one block per b), 512 threads = 16 warps.
// warp = (t-group of 8) x (m-band half: ml), two stages over m-halves.
// Inner math in packed f32x2 (FFMA2): t-pairs from transposed Xst.
// dyn smem: Xst 81*66 + Ws 81*256 floats
// ---------------------------------------------------------------------------
#define GATES_SMEM ((81 * 66 + 81 * 256) * 4)
__global__ void __launch_bounds__(512, 1)
k_gates(const float* __restrict__ X,
        const float* __restrict__ Wl,
        const float* __restrict__ s0) {
    extern __shared__ float sm[];
    float* Xst = sm;              // [k][t] transposed, pitch 66
    float* Ws  = sm + 81 * 66;    // [k][gate][c64]  (one m-half)
    int b = blockIdx.x;
    int tid = threadIdx.x;
    int wid = tid >> 5, lane = tid & 31;
    int wrow = (wid & 7) * 8;     // 8 t-rows per warp
    int ml = wid >> 3;            // which 32-col band within the 64-col half

    for (int idx = tid; idx < T_ * N_; idx += 512) {
        int t = idx / N_, k = idx - t * N_;
        Xst[k * 66 + t] = X[b * T_ * N_ + idx];
    }

    for (int stage = 0; stage < 2; stage++) {
        __syncthreads();
        for (int idx = tid; idx < 81 * 256; idx += 512) {
            int k = idx >> 8, j = idx & 255;
            int g = j >> 6, c = j & 63;
            Ws[idx] = Wl[k * G4_ + g * M_ + stage * 64 + c];
        }
        __syncthreads();

        unsigned long long acc[4][4];
#pragma unroll
        for (int g = 0; g < 4; g++)
#pragma unroll
            for (int p = 0; p < 4; p++) acc[g][p] = 0ull;

#pragma unroll 3
        for (int k = 0; k < 81; k++) {
            const float* xr = &Xst[k * 66 + wrow];
            unsigned long long x0 = *(const unsigned long long*)(xr + 0);
            unsigned long long x1 = *(const unsigned long long*)(xr + 2);
            unsigned long long x2 = *(const unsigned long long*)(xr + 4);
            unsigned long long x3 = *(const unsigned long long*)(xr + 6);
            int wk = k * 256 + ml * 32 + lane;
            float wi = Ws[wk +   0];
            float wf = Ws[wk +  64];
            float wg = Ws[wk + 128];
            float wo = Ws[wk + 192];
            unsigned long long di = pk2(wi, wi);
            unsigned long long df = pk2(wf, wf);
            unsigned long long dg = pk2(wg, wg);
            unsigned long long do_ = pk2(wo, wo);
            acc[0][0] = fma2(x0, di, acc[0][0]);
            acc[0][1] = fma2(x1, di, acc[0][1]);
            acc[0][2] = fma2(x2, di, acc[0][2]);
            acc[0][3] = fma2(x3, di, acc[0][3]);
            acc[1][0] = fma2(x0, df, acc[1][0]);
            acc[1][1] = fma2(x1, df, acc[1][1]);
            acc[1][2] = fma2(x2, df, acc[1][2]);
            acc[1][3] = fma2(x3, df, acc[1][3]);
            acc[2][0] = fma2(x0, dg, acc[2][0]);
            acc[2][1] = fma2(x1, dg, acc[2][1]);
            acc[2][2] = fma2(x2, dg, acc[2][2]);
            acc[2][3] = fma2(x3, dg, acc[2][3]);
            acc[3][0] = fma2(x0, do_, acc[3][0]);
            acc[3][1] = fma2(x1, do_, acc[3][1]);
            acc[3][2] = fma2(x2, do_, acc[3][2]);
            acc[3][3] = fma2(x3, do_, acc[3][3]);
        }

        int m = stage * 64 + ml * 32 + lane;
        float zi = g_z[b * G4_ + 0 * M_ + m];
        float zf = g_z[b * G4_ + 1 * M_ + m];
        float zg = g_z[b * G4_ + 2 * M_ + m];
        float zo = g_z[b * G4_ + 3 * M_ + m];
        float sv = s0[b * M_ + m];
#pragma unroll
        for (int p = 0; p < 4; p++) {
            float vi[2], vf[2], vg[2], vo[2];
            unpk2(acc[0][p], vi[0], vi[1]);
            unpk2(acc[1][p], vf[0], vf[1]);
            unpk2(acc[2][p], vg[0], vg[1]);
            unpk2(acc[3][p], vo[0], vo[1]);
#pragma unroll
            for (int h = 0; h < 2; h++) {
                int t = wrow + 2 * p + h;
                float iv = sigm(vi[h] + zi);
                float fv = sigm(vf[h] + zf);
                float gv = tanhe(vg[h] + zg);
                float ov = sigm(vo[h] + zo);
                float cc = fv * sv + iv * gv;
                float hh = ov * tanhe(cc);
                g_hc[(b * T_ + t) * 256 + m]       = hh;
                g_hc[(b * T_ + t) * 256 + M_ + m]  = cc;
            }
        }
    }
}

// ---------------------------------------------------------------------------
// K2 (fused): per b —
//   A[t,j]  = hc[t,:] @ We_w[:,j] + We_b[j]             (64x64, K=256)
//   U[i,k]  = sum_t X[b,t,i]*Ue_w[t,k] + Ue_b[k]        (81x64)
//   scores[t,i] = sum_k v[k]*tanh(A[t,k]+U[i,k]); alpha = softmax_i
// grid = B, 512 threads, dynamic smem.
// ---------------------------------------------------------------------------
#define AS_OFF  0
#define US_OFF  (64 * 65)                  // 4160
#define US_PAD  (96 * 65)                  // padded rows so lane+64 reads stay in-region
#define SC_OFF  (US_OFF + US_PAD)          // 10400 scratch
#define VS_OFF  (SC_OFF + 9280)            // 19680
#define UB_OFF  (VS_OFF + 64)              // 19744
#define ATTN_SMEM ((UB_OFF + 64) * 4)      // 79232 B
__global__ void __launch_bounds__(512, 1)
k_attn(const float* __restrict__ Wew, const float* __restrict__ Web,
       const float* __restrict__ X,   const float* __restrict__ Uew,
       const float* __restrict__ Ueb, const float* __restrict__ vew) {
    extern __shared__ float sm[];
    float* As = sm + AS_OFF;    // [t][k] pitch 65
    float* Us = sm + US_OFF;    // [i][k] pitch 65 (rows padded to 96)
    float* S  = sm + SC_OFF;    // scratch
    float* vs = sm + VS_OFF;
    float* ub = sm + UB_OFF;
    int b = blockIdx.x, tid = threadIdx.x;

    // ---- phase 1: A = hc @ We_w + We_b ----
    {
        float* hcs = S;            // 64*65
        float* Wes = S + 64 * 65;  // 64*64
        int r0 = (tid >> 4) * 2;
        int c0 = (tid & 15) * 4;
        float acc[2][4];
#pragma unroll
        for (int i = 0; i < 2; i++)
#pragma unroll
            for (int j = 0; j < 4; j++) acc[i][j] = Web[c0 + j];

        for (int kc = 0; kc < 4; kc++) {
            __syncthreads();
            for (int idx = tid; idx < 4096; idx += 512) {
                int t = idx >> 6, kk = idx & 63;
                hcs[t * 65 + kk] = g_hc[(b * T_ + t) * 256 + kc * 64 + kk];
            }
            for (int idx = tid; idx < 4096; idx += 512)
                Wes[idx] = Wew[kc * 4096 + idx];
            __syncthreads();
#pragma unroll 4
            for (int k = 0; k < 64; k++) {
                float a0 = hcs[r0 * 65 + k];
                float a1 = hcs[(r0 + 1) * 65 + k];
                float4 w = *(const float4*)&Wes[k * 64 + c0];
                acc[0][0] += a0 * w.x; acc[0][1] += a0 * w.y;
                acc[0][2] += a0 * w.z; acc[0][3] += a0 * w.w;
                acc[1][0] += a1 * w.x; acc[1][1] += a1 * w.y;
                acc[1][2] += a1 * w.z; acc[1][3] += a1 * w.w;
            }
        }
#pragma unroll
        for (int i = 0; i < 2; i++)
#pragma unroll
            for (int j = 0; j < 4; j++)
                As[(r0 + i) * 65 + c0 + j] = acc[i][j];
    }

    // ---- phase 2: U ----
    __syncthreads();
    {
        float* Xs  = S;            // 5184
        float* Ues = S + 5184;     // 4096
        for (int idx = tid; idx < 5184; idx += 512) Xs[idx] = X[b * 5184 + idx];
        for (int idx = tid; idx < 4096; idx += 512) Ues[idx] = Uew[idx];
        if (tid < 64)                vs[tid]       = vew[tid];
        else if (tid < 128)          ub[tid - 64]  = Ueb[tid - 64];
        __syncthreads();

        if (tid < 336) {
            int ig = tid >> 4, kq = tid & 15, i0 = ig * 4;
            int ni = (i0 + 4 <= N_) ? 4 : (N_ - i0);
            float4 bias = *(const float4*)&ub[kq * 4];
            float4 a0 = bias, a1 = bias, a2 = bias, a3 = bias;
#pragma unroll 4
            for (int t = 0; t < T_; t++) {
                float4 u = *(const float4*)&Ues[t * 64 + kq * 4];
                const float* xr = &Xs[t * N_ + i0];
                float x0 = xr[0], x1 = xr[1], x2 = xr[2], x3 = xr[3];
                a0.x += x0 * u.x; a0.y += x0 * u.y; a0.z += x0 * u.z; a0.w += x0 * u.w;
                a1.x += x1 * u.x; a1.y += x1 * u.y; a1.z += x1 * u.z; a1.w += x1 * u.w;
                a2.x += x2 * u.x; a2.y += x2 * u.y; a2.z += x2 * u.z; a2.w += x2 * u.w;
                a3.x += x3 * u.x; a3.y += x3 * u.y; a3.z += x3 * u.z; a3.w += x3 * u.w;
            }
            float4 av[4] = {a0, a1, a2, a3};
            for (int j = 0; j < ni; j++) {
                float* up = &Us[(i0 + j) * 65 + kq * 4];
                up[0] = av[j].x; up[1] = av[j].y; up[2] = av[j].z; up[3] = av[j].w;
            }
        }
    }

    // ---- phase 3: scores + softmax + alpha ----
    __syncthreads();
    {
        int wid = tid >> 5, lane = tid & 31;
        bool v2 = (lane + 64 < N_);
        for (int t = wid; t < T_; t += 16) {
            float a0 = 0.f, a1 = 0.f, a2 = 0.f;
            const float* Ap = &As[t * 65];
            const float* U0 = &Us[lane * 65];
            const float* U1 = &Us[(lane + 32) * 65];
            const float* U2 = &Us[(lane + 64) * 65];  // padded region: safe read
#pragma unroll 4
            for (int k = 0; k < 64; k++) {
                float av = Ap[k], vv = vs[k];
                a0 += vv * tanhap(av + U0[k]);
                a1 += vv * tanhap(av + U1[k]);
                a2 += vv * tanhap(av + U2[k]);
            }
            if (!v2) a2 = -1e30f;
            float mx = fmaxf(fmaxf(a0, a1), a2);
#pragma unroll
            for (int off = 16; off; off >>= 1)
                mx = fmaxf(mx, __shfl_xor_sync(0xffffffffu, mx, off));
            float e0 = __expf(a0 - mx);
            float e1 = __expf(a1 - mx);
            float e2 = __expf(a2 - mx);   // 0 when invalid (a2=-1e30)
            float sum = e0 + e1 + e2;
#pragma unroll
            for (int off = 16; off; off >>= 1)
                sum += __shfl_xor_sync(0xffffffffu, sum, off);
            float inv = frcp(sum);
            float* ap = &g_alpha[b * (T_ * N_) + t * N_];
            ap[lane]      = e0 * inv;
            ap[lane + 32] = e1 * inv;
            if (v2) ap[lane + 64] = e2 * inv;
        }
    }
}

// ---------------------------------------------------------------------------
// K3: out[t,b,tp,i] = X[b,tp,i] * alpha[b,t,i]
// grid = B*8 (b, t-group of 8), 256 threads; X staged once per block.
// ---------------------------------------------------------------------------
__global__ void k_out(const float* __restrict__ X, float* __restrict__ out) {
    __shared__ float Xs[T_ * N_];      // 5184
    __shared__ float al[8 * N_];
    int b = blockIdx.x >> 3, tg = blockIdx.x & 7;
    int tid = threadIdx.x;             // 256
    for (int idx = tid; idx < T_ * N_; idx += 256) Xs[idx] = X[b * T_ * N_ + idx];
    for (int idx = tid; idx < 8 * N_; idx += 256)
        al[idx] = g_alpha[b * (T_ * N_) + tg * 8 * N_ + idx];
    __syncthreads();
    for (int tt = 0; tt < 8; tt++) {
        int t = tg * 8 + tt;
        float4* O4 = (float4*)out + (size_t)(t * B_ + b) * 1296;
        const float* alp = &al[tt * N_];
        for (int j4 = tid; j4 < 1296; j4 += 256) {
            float4 x = *(const float4*)&Xs[j4 * 4];
            int jb = j4 * 4;
            int i0 = jb % N_;
            int i1 = i0 + 1; if (i1 >= N_) i1 -= N_;
            int i2 = i1 + 1; if (i2 >= N_) i2 -= N_;
            int i3 = i2 + 1; if (i3 >= N_) i3 -= N_;
            float4 o;
            o.x = x.x * alp[i0]; o.y = x.y * alp[i1];
            o.z = x.z * alp[i2]; o.w = x.w * alp[i3];
            O4[j4] = o;
        }
    }
}

// ---------------------------------------------------------------------------
extern "C" void kernel_launch(void* const* d_in, const int* in_sizes, int n_in,
                              void* d_out, int out_size) {
    const float* X   = (const float*)d_in[0];
    const float* h0  = (const float*)d_in[1];
    const float* s0  = (const float*)d_in[2];
    const float* Wl  = (const float*)d_in[3];
    const float* Ul  = (const float*)d_in[4];
    const float* bl  = (const float*)d_in[5];
    const float* Wew = (const float*)d_in[6];
    const float* Web = (const float*)d_in[7];
    const float* Uew = (const float*)d_in[8];
    const float* Ueb = (const float*)d_in[9];
    const float* vew = (const float*)d_in[10];
    // d_in[11] = ve_b: constant pre-softmax shift -> softmax-invariant, unused.
    float* out = (float*)d_out;

    cudaFuncSetAttribute(k_gates, cudaFuncAttributeMaxDynamicSharedMemorySize, GATES_SMEM);
    cudaFuncSetAttribute(k_attn,  cudaFuncAttributeMaxDynamicSharedMemorySize, ATTN_SMEM);

    k_z    <<<B_,     G4_>>>(h0, Ul, bl);
    k_gates<<<B_,     512, GATES_SMEM>>>(X, Wl, s0);
    k_attn <<<B_,     512, ATTN_SMEM>>>(Wew, Web, X, Uew, Ueb, vew);
    k_out  <<<B_ * 8, 256>>>(X, out);
    (void)in_sizes; (void)n_in; (void)out_size;
}

// round 4
// speedup vs baseline: 1.5305x; 1.0126x over previous
#include <cuda_runtime.h>

#define B_  128
#define T_  64
#define N_  81
#define M_  128
#define G4_ 512

// scratch (static device globals — no allocs)
__device__ float g_z[B_ * G4_];            // h0@U_lstm + b_lstm     (128,512)
__device__ float g_hc[B_ * T_ * 2 * M_];   // [h;c]                  (128,64,256)
__device__ float g_alpha[B_ * T_ * N_];    // softmax(scores)        (128,64,81)

__device__ __forceinline__ float frcp(float x) {
    float r; asm("rcp.approx.ftz.f32 %0, %1;" : "=f"(r) : "f"(x)); return r;
}
__device__ __forceinline__ float sigm(float x) {
    return frcp(1.0f + __expf(-x));
}
__device__ __forceinline__ float tanhe(float x) {           // exp-based, accurate
    return 2.0f * frcp(1.0f + __expf(-2.0f * x)) - 1.0f;
}
__device__ __forceinline__ float tanhap(float x) {          // HW tanh, 1 MUFU
    float r; asm("tanh.approx.f32 %0, %1;" : "=f"(r) : "f"(x)); return r;
}
__device__ __forceinline__ unsigned long long pk2(float a, float b) {
    unsigned long long r;
    asm("mov.b64 %0, {%1, %2};" : "=l"(r) : "f"(a), "f"(b)); return r;
}
__device__ __forceinline__ unsigned long long fma2(unsigned long long a,
                                                   unsigned long long b,
                                                   unsigned long long c) {
    unsigned long long d;
    asm("fma.rn.f32x2 %0, %1, %2, %3;" : "=l"(d) : "l"(a), "l"(b), "l"(c));
    return d;
}
__device__ __forceinline__ void unpk2(unsigned long long v, float& lo, float& hi) {
    asm("mov.b64 {%0, %1}, %2;" : "=f"(lo), "=f"(hi) : "l"(v));
}

// ---------------------------------------------------------------------------
// K0: z[b,g] = b_lstm[g] + sum_k h0[b,k] * U_lstm[k,g]
// ---------------------------------------------------------------------------
__global__ void k_z(const float* __restrict__ h0,
                    const float* __restrict__ Ul,
                    const float* __restrict__ bl) {
    __shared__ float hs[M_];
    int b = blockIdx.x, g = threadIdx.x;           // 512 threads
    if (g < M_) hs[g] = h0[b * M_ + g];
    __syncthreads();
    float acc = bl[g];
#pragma unroll 8
    for (int k = 0; k < M_; k++) acc += hs[k] * Ul[k * G4_ + g];
    g_z[b * G4_ + g] = acc;
}

// ---------------------------------------------------------------------------
// K1: gates = X@W_lstm + z ; LSTM cell ; store hc = [h;c]
// grid = B (one block per b), 512 threads = 16 warps.
// warp = (t-group of 8) x (m-band half: ml), two stages over m-halves.
// Inner math in packed f32x2 (FFMA2): t-pairs from transposed Xst.
// dyn smem: Xst 81*66 + Ws 81*256 floats
// ---------------------------------------------------------------------------
#define GATES_SMEM ((81 * 66 + 81 * 256) * 4)
__global__ void __launch_bounds__(512, 1)
k_gates(const float* __restrict__ X,
        const float* __restrict__ Wl,
        const float* __restrict__ s0) {
    extern __shared__ float sm[];
    float* Xst = sm;              // [k][t] transposed, pitch 66
    float* Ws  = sm + 81 * 66;    // [k][gate][c64]  (one m-half)
    int b = blockIdx.x;
    int tid = threadIdx.x;
    int wid = tid >> 5, lane = tid & 31;
    int wrow = (wid & 7) * 8;     // 8 t-rows per warp
    int ml = wid >> 3;            // which 32-col band within the 64-col half

    for (int idx = tid; idx < T_ * N_; idx += 512) {
        int t = idx / N_, k = idx - t * N_;
        Xst[k * 66 + t] = X[b * T_ * N_ + idx];
    }

    for (int stage = 0; stage < 2; stage++) {
        __syncthreads();
        for (int idx = tid; idx < 81 * 256; idx += 512) {
            int k = idx >> 8, j = idx & 255;
            int g = j >> 6, c = j & 63;
            Ws[idx] = Wl[k * G4_ + g * M_ + stage * 64 + c];
        }
        __syncthreads();

        unsigned long long acc[4][4];
#pragma unroll
        for (int g = 0; g < 4; g++)
#pragma unroll
            for (int p = 0; p < 4; p++) acc[g][p] = 0ull;

#pragma unroll 3
        for (int k = 0; k < 81; k++) {
            const float* xr = &Xst[k * 66 + wrow];
            unsigned long long x0 = *(const unsigned long long*)(xr + 0);
            unsigned long long x1 = *(const unsigned long long*)(xr + 2);
            unsigned long long x2 = *(const unsigned long long*)(xr + 4);
            unsigned long long x3 = *(const unsigned long long*)(xr + 6);
            int wk = k * 256 + ml * 32 + lane;
            float wi = Ws[wk +   0];
            float wf = Ws[wk +  64];
            float wg = Ws[wk + 128];
            float wo = Ws[wk + 192];
            unsigned long long di = pk2(wi, wi);
            unsigned long long df = pk2(wf, wf);
            unsigned long long dg = pk2(wg, wg);
            unsigned long long do_ = pk2(wo, wo);
            acc[0][0] = fma2(x0, di, acc[0][0]);
            acc[0][1] = fma2(x1, di, acc[0][1]);
            acc[0][2] = fma2(x2, di, acc[0][2]);
            acc[0][3] = fma2(x3, di, acc[0][3]);
            acc[1][0] = fma2(x0, df, acc[1][0]);
            acc[1][1] = fma2(x1, df, acc[1][1]);
            acc[1][2] = fma2(x2, df, acc[1][2]);
            acc[1][3] = fma2(x3, df, acc[1][3]);
            acc[2][0] = fma2(x0, dg, acc[2][0]);
            acc[2][1] = fma2(x1, dg, acc[2][1]);
            acc[2][2] = fma2(x2, dg, acc[2][2]);
            acc[2][3] = fma2(x3, dg, acc[2][3]);
            acc[3][0] = fma2(x0, do_, acc[3][0]);
            acc[3][1] = fma2(x1, do_, acc[3][1]);
            acc[3][2] = fma2(x2, do_, acc[3][2]);
            acc[3][3] = fma2(x3, do_, acc[3][3]);
        }

        int m = stage * 64 + ml * 32 + lane;
        float zi = g_z[b * G4_ + 0 * M_ + m];
        float zf = g_z[b * G4_ + 1 * M_ + m];
        float zg = g_z[b * G4_ + 2 * M_ + m];
        float zo = g_z[b * G4_ + 3 * M_ + m];
        float sv = s0[b * M_ + m];
#pragma unroll
        for (int p = 0; p < 4; p++) {
            float vi[2], vf[2], vg[2], vo[2];
            unpk2(acc[0][p], vi[0], vi[1]);
            unpk2(acc[1][p], vf[0], vf[1]);
            unpk2(acc[2][p], vg[0], vg[1]);
            unpk2(acc[3][p], vo[0], vo[1]);
#pragma unroll
            for (int h = 0; h < 2; h++) {
                int t = wrow + 2 * p + h;
                float iv = sigm(vi[h] + zi);
                float fv = sigm(vf[h] + zf);
                float gv = tanhe(vg[h] + zg);
                float ov = sigm(vo[h] + zo);
                float cc = fv * sv + iv * gv;
                float hh = ov * tanhe(cc);
                g_hc[(b * T_ + t) * 256 + m]       = hh;
                g_hc[(b * T_ + t) * 256 + M_ + m]  = cc;
            }
        }
    }
}

// ---------------------------------------------------------------------------
// K2 (fused): per b —
//   A[t,j]  = hc[t,:] @ We_w[:,j] + We_b[j]             (64x64, K=256)
//   U[i,k]  = sum_t X[b,t,i]*Ue_w[t,k] + Ue_b[k]        (81x64)
//   scores[t,i] = sum_k v[k]*tanh(A[t,k]+U[i,k]); alpha = softmax_i
// grid = B, 512 threads, dynamic smem.
// ---------------------------------------------------------------------------
#define AS_OFF  0
#define US_OFF  (64 * 65)                  // 4160
#define US_PAD  (96 * 65)                  // padded rows so lane+64 reads stay in-region
#define SC_OFF  (US_OFF + US_PAD)          // 10400 scratch
#define VS_OFF  (SC_OFF + 9280)            // 19680
#define UB_OFF  (VS_OFF + 64)              // 19744
#define ATTN_SMEM ((UB_OFF + 64) * 4)      // 79232 B
__global__ void __launch_bounds__(512, 1)
k_attn(const float* __restrict__ Wew, const float* __restrict__ Web,
       const float* __restrict__ X,   const float* __restrict__ Uew,
       const float* __restrict__ Ueb, const float* __restrict__ vew) {
    extern __shared__ float sm[];
    float* As = sm + AS_OFF;    // [t][k] pitch 65
    float* Us = sm + US_OFF;    // [i][k] pitch 65 (rows padded to 96)
    float* S  = sm + SC_OFF;    // scratch
    float* vs = sm + VS_OFF;
    float* ub = sm + UB_OFF;
    int b = blockIdx.x, tid = threadIdx.x;

    // ---- phase 1: A = hc @ We_w + We_b ----
    {
        float* hcs = S;            // 64*65
        float* Wes = S + 64 * 65;  // 64*64
        int r0 = (tid >> 4) * 2;
        int c0 = (tid & 15) * 4;
        float acc[2][4];
#pragma unroll
        for (int i = 0; i < 2; i++)
#pragma unroll
            for (int j = 0; j < 4; j++) acc[i][j] = Web[c0 + j];

        for (int kc = 0; kc < 4; kc++) {
            __syncthreads();
            for (int idx = tid; idx < 4096; idx += 512) {
                int t = idx >> 6, kk = idx & 63;
                hcs[t * 65 + kk] = g_hc[(b * T_ + t) * 256 + kc * 64 + kk];
            }
            for (int idx = tid; idx < 4096; idx += 512)
                Wes[idx] = Wew[kc * 4096 + idx];
            __syncthreads();
#pragma unroll 4
            for (int k = 0; k < 64; k++) {
                float a0 = hcs[r0 * 65 + k];
                float a1 = hcs[(r0 + 1) * 65 + k];
                float4 w = *(const float4*)&Wes[k * 64 + c0];
                acc[0][0] += a0 * w.x; acc[0][1] += a0 * w.y;
                acc[0][2] += a0 * w.z; acc[0][3] += a0 * w.w;
                acc[1][0] += a1 * w.x; acc[1][1] += a1 * w.y;
                acc[1][2] += a1 * w.z; acc[1][3] += a1 * w.w;
            }
        }
#pragma unroll
        for (int i = 0; i < 2; i++)
#pragma unroll
            for (int j = 0; j < 4; j++)
                As[(r0 + i) * 65 + c0 + j] = acc[i][j];
    }

    // ---- phase 2: U ----
    __syncthreads();
    {
        float* Xs  = S;            // 5184
        float* Ues = S + 5184;     // 4096
        for (int idx = tid; idx < 5184; idx += 512) Xs[idx] = X[b * 5184 + idx];
        for (int idx = tid; idx < 4096; idx += 512) Ues[idx] = Uew[idx];
        if (tid < 64)                vs[tid]       = vew[tid];
        else if (tid < 128)          ub[tid - 64]  = Ueb[tid - 64];
        __syncthreads();

        if (tid < 336) {
            int ig = tid >> 4, kq = tid & 15, i0 = ig * 4;
            int ni = (i0 + 4 <= N_) ? 4 : (N_ - i0);
            float4 bias = *(const float4*)&ub[kq * 4];
            float4 a0 = bias, a1 = bias, a2 = bias, a3 = bias;
#pragma unroll 4
            for (int t = 0; t < T_; t++) {
                float4 u = *(const float4*)&Ues[t * 64 + kq * 4];
                const float* xr = &Xs[t * N_ + i0];
                float x0 = xr[0], x1 = xr[1], x2 = xr[2], x3 = xr[3];
                a0.x += x0 * u.x; a0.y += x0 * u.y; a0.z += x0 * u.z; a0.w += x0 * u.w;
                a1.x += x1 * u.x; a1.y += x1 * u.y; a1.z += x1 * u.z; a1.w += x1 * u.w;
                a2.x += x2 * u.x; a2.y += x2 * u.y; a2.z += x2 * u.z; a2.w += x2 * u.w;
                a3.x += x3 * u.x; a3.y += x3 * u.y; a3.z += x3 * u.z; a3.w += x3 * u.w;
            }
            float4 av[4] = {a0, a1, a2, a3};
            for (int j = 0; j < ni; j++) {
                float* up = &Us[(i0 + j) * 65 + kq * 4];
                up[0] = av[j].x; up[1] = av[j].y; up[2] = av[j].z; up[3] = av[j].w;
            }
        }
    }

    // ---- phase 3: scores + softmax + alpha ----
    __syncthreads();
    {
        int wid = tid >> 5, lane = tid & 31;
        bool v2 = (lane + 64 < N_);
        for (int t = wid; t < T_; t += 16) {
            float a0 = 0.f, a1 = 0.f, a2 = 0.f;
            const float* Ap = &As[t * 65];
            const float* U0 = &Us[lane * 65];
            const float* U1 = &Us[(lane + 32) * 65];
            const float* U2 = &Us[(lane + 64) * 65];  // padded region: safe read
#pragma unroll 4
            for (int k = 0; k < 64; k++) {
                float av = Ap[k], vv = vs[k];
                a0 += vv * tanhap(av + U0[k]);
                a1 += vv * tanhap(av + U1[k]);
                a2 += vv * tanhap(av + U2[k]);
            }
            if (!v2) a2 = -1e30f;
            float mx = fmaxf(fmaxf(a0, a1), a2);
#pragma unroll
            for (int off = 16; off; off >>= 1)
                mx = fmaxf(mx, __shfl_xor_sync(0xffffffffu, mx, off));
            float e0 = __expf(a0 - mx);
            float e1 = __expf(a1 - mx);
            float e2 = __expf(a2 - mx);   // 0 when invalid (a2=-1e30)
            float sum = e0 + e1 + e2;
#pragma unroll
            for (int off = 16; off; off >>= 1)
                sum += __shfl_xor_sync(0xffffffffu, sum, off);
            float inv = frcp(sum);
            float* ap = &g_alpha[b * (T_ * N_) + t * N_];
            ap[lane]      = e0 * inv;
            ap[lane + 32] = e1 * inv;
            if (v2) ap[lane + 64] = e2 * inv;
        }
    }
}

// ---------------------------------------------------------------------------
// K3: out[t,b,tp,i] = X[b,tp,i] * alpha[b,t,i]
// grid = B*8 (b, t-group of 8), 256 threads; X staged once per block.
// ---------------------------------------------------------------------------
__global__ void k_out(const float* __restrict__ X, float* __restrict__ out) {
    __shared__ float Xs[T_ * N_];      // 5184
    __shared__ float al[8 * N_];
    int b = blockIdx.x >> 3, tg = blockIdx.x & 7;
    int tid = threadIdx.x;             // 256
    for (int idx = tid; idx < T_ * N_; idx += 256) Xs[idx] = X[b * T_ * N_ + idx];
    for (int idx = tid; idx < 8 * N_; idx += 256)
        al[idx] = g_alpha[b * (T_ * N_) + tg * 8 * N_ + idx];
    __syncthreads();
    for (int tt = 0; tt < 8; tt++) {
        int t = tg * 8 + tt;
        float4* O4 = (float4*)out + (size_t)(t * B_ + b) * 1296;
        const float* alp = &al[tt * N_];
        for (int j4 = tid; j4 < 1296; j4 += 256) {
            float4 x = *(const float4*)&Xs[j4 * 4];
            int jb = j4 * 4;
            int i0 = jb % N_;
            int i1 = i0 + 1; if (i1 >= N_) i1 -= N_;
            int i2 = i1 + 1; if (i2 >= N_) i2 -= N_;
            int i3 = i2 + 1; if (i3 >= N_) i3 -= N_;
            float4 o;
            o.x = x.x * alp[i0]; o.y = x.y * alp[i1];
            o.z = x.z * alp[i2]; o.w = x.w * alp[i3];
            O4[j4] = o;
        }
    }
}

// ---------------------------------------------------------------------------
extern "C" void kernel_launch(void* const* d_in, const int* in_sizes, int n_in,
                              void* d_out, int out_size) {
    const float* X   = (const float*)d_in[0];
    const float* h0  = (const float*)d_in[1];
    const float* s0  = (const float*)d_in[2];
    const float* Wl  = (const float*)d_in[3];
    const float* Ul  = (const float*)d_in[4];
    const float* bl  = (const float*)d_in[5];
    const float* Wew = (const float*)d_in[6];
    const float* Web = (const float*)d_in[7];
    const float* Uew = (const float*)d_in[8];
    const float* Ueb = (const float*)d_in[9];
    const float* vew = (const float*)d_in[10];
    // d_in[11] = ve_b: constant pre-softmax shift -> softmax-invariant, unused.
    float* out = (float*)d_out;

    cudaFuncSetAttribute(k_gates, cudaFuncAttributeMaxDynamicSharedMemorySize, GATES_SMEM);
    cudaFuncSetAttribute(k_attn,  cudaFuncAttributeMaxDynamicSharedMemorySize, ATTN_SMEM);

    k_z    <<<B_,     G4_>>>(h0, Ul, bl);
    k_gates<<<B_,     512, GATES_SMEM>>>(X, Wl, s0);
    k_attn <<<B_,     512, ATTN_SMEM>>>(Wew, Web, X, Uew, Ueb, vew);
    k_out  <<<B_ * 8, 256>>>(X, out);
    (void)in_sizes; (void)n_in; (void)out_size;
}